// round 15
// baseline (speedup 1.0000x reference)
#include <cuda_runtime.h>
#include <cstdint>

#define D     4096
#define TPB   256
#define NWARP (TPB / 32)
#define ROWB  (D * 4)            // 16384 bytes per row
#define ZCHUNK 4096              // SMEM zero buffer size (bytes)

// Forced re-read (asm volatile so the compiler cannot CSE it with the pass-1
// loads and keep 16 registers alive across barriers).
__device__ __forceinline__ float4 reload4(const float4* p) {
    float4 v;
    asm volatile("ld.global.ca.v4.f32 {%0,%1,%2,%3}, [%4];"
                 : "=f"(v.x), "=f"(v.y), "=f"(v.z), "=f"(v.w)
                 : "l"(p));
    return v;
}

// Exact top-2 merge of two (hi,lo) pairs (handles duplicates correctly).
__device__ __forceinline__ void merge2(float h2, float l2, float& hi, float& lo) {
    float nh = fmaxf(hi, h2);
    lo = fmaxf(fminf(hi, h2), fmaxf(lo, l2));
    hi = nh;
}

// 50-step bisection, fp32 op-for-op identical to the reference trajectory.
// mask = (sum(Z)-1 >= 0). With p = 1/4095, u^p in [0.975, 1] for every
// positive fp32 u, so mask <=> count(Xs_j > t) >= 2, except count==1 where
// sum = powf(u1,p) can round to >= 1.0f only for u1 within ~1e-4 of 1.
// That edge needs H - L >= 0.999; when H - L < 0.998 the loop is provably
// pure "t < L" -> branchless form. Early exit: once t = t_min + diff rounds
// to t_min the trajectory is frozen and the reference's final t == t_min.
__device__ __forceinline__ float bisect_t(float Hraw, float Lraw) {
    const float H = __fmul_rn(0.5f, Hraw);   // Xs = 0.5*X, exact & monotone
    const float L = __fmul_rn(0.5f, Lraw);
    const float p = (float)(1.0 / 4095.0);
    float t_min = H - 1.0f;                  // m - 1
    float t_max = H - 0.015625f;             // m - 4096^(1-1.5)
    float diff  = t_max - t_min;
    float t     = t_min;
    if (H - L < 0.998f) {
        #pragma unroll 1
        for (int it = 0; it < 50; it++) {
            diff *= 0.5f;
            t = t_min + diff;
            if (t == t_min) break;
            t_min = (t < L) ? t : t_min;
        }
    } else {
        #pragma unroll 1
        for (int it = 0; it < 50; it++) {
            diff *= 0.5f;
            t = t_min + diff;
            if (t == t_min) break;
            bool mask;
            if (t < L) {
                mask = true;
            } else {
                float u1 = H - t;
                mask = (u1 >= 0.999f) ? (powf(u1, p) >= 1.0f) : false;
            }
            if (mask) t_min = t;
        }
    }
    return t;
}

__global__ __launch_bounds__(TPB, 8)
void entmax_bisect_kernel(const float* __restrict__ X, float* __restrict__ Y) {
    const int tid  = threadIdx.x;
    const int lane = tid & 31;
    const int wid  = tid >> 5;
    const size_t base = (size_t)blockIdx.x * D;

    __shared__ float4 zbuf[ZCHUNK / 16];     // 4 KB of zeros for bulk stores
    __shared__ float s_h[NWARP], s_l[NWARP];
    __shared__ float s_t;
    __shared__ float s_S;

    const float4* Xv = reinterpret_cast<const float4*>(X + base);
    float*        Yrow = Y + base;

    // ---- Zero the SMEM staging buffer (one STS.128 per thread) ----
    zbuf[tid] = make_float4(0.0f, 0.0f, 0.0f, 0.0f);
    if (tid == 0) s_S = 0.0f;
    __syncthreads();                                      // b0: zbuf ready

    // ---- Thread 0: bulk-store zeros over the whole output row via the
    // async (TMA) path. 4 x 4KB ops replace 1024 lane STG.128 -> the zero
    // write stream costs ~nothing on the LSU and overlaps everything. ----
    if (tid == 0) {
        uint32_t zaddr = (uint32_t)__cvta_generic_to_shared(zbuf);
        asm volatile("fence.proxy.async.shared::cta;" ::: "memory");
        #pragma unroll
        for (int k = 0; k < ROWB / ZCHUNK; k++) {
            asm volatile(
                "cp.async.bulk.global.shared::cta.bulk_group [%0], [%1], %2;"
                :: "l"(reinterpret_cast<char*>(Yrow) + k * ZCHUNK),
                   "r"(zaddr), "r"(ZCHUNK)
                : "memory");
        }
        asm volatile("cp.async.bulk.commit_group;" ::: "memory");
    }

    // ---- Pass 1: load 16 values, TREE top-2 fold ----
    float hi, lo;
    {
        float4 f0 = Xv[tid];
        float4 f1 = Xv[TPB + tid];
        float4 f2 = Xv[2 * TPB + tid];
        float4 f3 = Xv[3 * TPB + tid];

        float h0a = fmaxf(f0.x, f0.y), l0a = fminf(f0.x, f0.y);
        float h0b = fmaxf(f0.z, f0.w), l0b = fminf(f0.z, f0.w);
        float h0 = fmaxf(h0a, h0b), l0 = fmaxf(fminf(h0a, h0b), fmaxf(l0a, l0b));

        float h1a = fmaxf(f1.x, f1.y), l1a = fminf(f1.x, f1.y);
        float h1b = fmaxf(f1.z, f1.w), l1b = fminf(f1.z, f1.w);
        float h1 = fmaxf(h1a, h1b), l1 = fmaxf(fminf(h1a, h1b), fmaxf(l1a, l1b));

        float h2a = fmaxf(f2.x, f2.y), l2a = fminf(f2.x, f2.y);
        float h2b = fmaxf(f2.z, f2.w), l2b = fminf(f2.z, f2.w);
        float h2 = fmaxf(h2a, h2b), l2 = fmaxf(fminf(h2a, h2b), fmaxf(l2a, l2b));

        float h3a = fmaxf(f3.x, f3.y), l3a = fminf(f3.x, f3.y);
        float h3b = fmaxf(f3.z, f3.w), l3b = fminf(f3.z, f3.w);
        float h3 = fmaxf(h3a, h3b), l3 = fmaxf(fminf(h3a, h3b), fmaxf(l3a, l3b));

        merge2(h1, l1, h0, l0);
        merge2(h3, l3, h2, l2);
        merge2(h2, l2, h0, l0);
        hi = h0; lo = l0;
    }
    const float thi = hi;                    // per-thread raw max

    // ---- Warp butterfly top-2 ----
    #pragma unroll
    for (int off = 16; off > 0; off >>= 1) {
        float oh = __shfl_xor_sync(0xffffffffu, hi, off);
        float ol = __shfl_xor_sync(0xffffffffu, lo, off);
        float nh = fmaxf(hi, oh);
        lo = fmaxf(fmaxf(lo, ol), fminf(hi, oh));
        hi = nh;
    }
    if (lane == 0) { s_h[wid] = hi; s_l[wid] = lo; }
    __syncthreads();                                      // b1

    // ---- Thread 0 only: combine 8 warps' top-2 (tree) + scalar bisection ----
    if (tid == 0) {
        float Hb = s_h[0], Lb = s_l[0];
        float h1 = s_h[1], l1 = s_l[1];
        float h2 = s_h[2], l2 = s_l[2];
        float h3 = s_h[3], l3 = s_l[3];
        float h4 = s_h[4], l4 = s_l[4];
        float h5 = s_h[5], l5 = s_l[5];
        float h6 = s_h[6], l6 = s_l[6];
        float h7 = s_h[7], l7 = s_l[7];
        merge2(h1, l1, Hb, Lb);
        merge2(h3, l3, h2, l2);
        merge2(h5, l5, h4, l4);
        merge2(h7, l7, h6, l6);
        merge2(h2, l2, Hb, Lb);
        merge2(h6, l6, h4, l4);
        merge2(h4, l4, Hb, Lb);
        s_t = bisect_t(Hb, Lb);
    }
    __syncthreads();                                      // b2

    const float t = s_t;
    const float p = (float)(1.0 / 4095.0);
    const bool hot = (__fmul_rn(0.5f, thi) > t);          // exact: x0.5 monotone

    // ---- Pass 2 (hot threads, ~1-3 per row): re-read, atomic-add z sum ----
    if (hot) {
        float sum = 0.0f;
        #pragma unroll
        for (int k = 0; k < 4; k++) {
            float4 g = reload4(Xv + k * TPB + tid);
            float u;
            u = __fmul_rn(0.5f, g.x) - t; if (u > 0.0f) sum += powf(u, p);
            u = __fmul_rn(0.5f, g.y) - t; if (u > 0.0f) sum += powf(u, p);
            u = __fmul_rn(0.5f, g.z) - t; if (u > 0.0f) sum += powf(u, p);
            u = __fmul_rn(0.5f, g.w) - t; if (u > 0.0f) sum += powf(u, p);
        }
        atomicAdd(&s_S, sum);
    }

    // Thread 0 drains its bulk-store group so the zero fill is globally
    // complete before any hot overwrite issued after b3.
    if (tid == 0) {
        asm volatile("cp.async.bulk.wait_group %0;" :: "n"(0) : "memory");
    }
    __syncthreads();                                      // b3

    const float S = s_S;

    // ---- Epilogue: hot threads overwrite ONLY the nonzero scalars ----
    if (hot) {
        const float rinv = 1.0f / S;                      // S > 0 always
        #pragma unroll
        for (int k = 0; k < 4; k++) {
            float4 g = reload4(Xv + k * TPB + tid);       // L1 hit
            const int e = (k * TPB + tid) * 4;
            float u;
            u = __fmul_rn(0.5f, g.x) - t; if (u > 0.0f) Yrow[e+0] = powf(u, p) * rinv;
            u = __fmul_rn(0.5f, g.y) - t; if (u > 0.0f) Yrow[e+1] = powf(u, p) * rinv;
            u = __fmul_rn(0.5f, g.z) - t; if (u > 0.0f) Yrow[e+2] = powf(u, p) * rinv;
            u = __fmul_rn(0.5f, g.w) - t; if (u > 0.0f) Yrow[e+3] = powf(u, p) * rinv;
        }
    }
}

extern "C" void kernel_launch(void* const* d_in, const int* in_sizes, int n_in,
                              void* d_out, int out_size) {
    const float* X = (const float*)d_in[0];
    float* Y = (float*)d_out;
    const int rows = in_sizes[0] / D;                     // 16384
    entmax_bisect_kernel<<<rows, TPB>>>(X, Y);
}